// round 10
// baseline (speedup 1.0000x reference)
#include <cuda_runtime.h>
#include <cstdint>
#include <cstddef>

// ---------------------------------------------------------------------------
// NSHE: 3 per-type linear encoders (+ReLU)  ->  GCN linear  ->  edge
// gather*weight scatter-add (segment_sum)   ->  row L2-normalize.
// All fp32. Scratch lives in __device__ globals (no allocation).
// ---------------------------------------------------------------------------

#define NMAX 200000
#define D 64

__device__ float g_enc[(size_t)NMAX * D];
__device__ float g_support[(size_t)NMAX * D];

// ---- packed f32x2 helpers (Blackwell sm_103a) -----------------------------
__device__ __forceinline__ unsigned long long fma2(unsigned long long a,
                                                   unsigned long long b,
                                                   unsigned long long c) {
    unsigned long long d;
    asm("fma.rn.f32x2 %0, %1, %2, %3;" : "=l"(d) : "l"(a), "l"(b), "l"(c));
    return d;
}
__device__ __forceinline__ unsigned long long splat2(float x) {
    unsigned long long d;
    asm("mov.b64 %0, {%1, %1};" : "=l"(d) : "f"(x));
    return d;
}
__device__ __forceinline__ void unpack2(unsigned long long v, float& lo, float& hi) {
    asm("mov.b64 {%0, %1}, %2;" : "=f"(lo), "=f"(hi) : "l"(v));
}

// ---------------------------------------------------------------------------
// GEMM: out[n,64] = act(A[n,K] @ W[K,64] + bias), act = relu or identity.
// Tile: 256 rows x 64 cols per block, 256 threads, 8x8 micro-tile per thread,
// accumulators as f32x2 pairs along N (B pairs are contiguous -> no pack movs
// for B; only 8 a-splats per k vs 32 FFMA2 -> fma-pipe bound).
// ---------------------------------------------------------------------------
template <int K, bool RELU>
__global__ void __launch_bounds__(256)
gemm_kernel(const float* __restrict__ A, const float* __restrict__ W,
            const float* __restrict__ bias, float* __restrict__ out, int nRows)
{
    constexpr int KT = 16;
    __shared__ float  sA[KT][260];   // transposed A tile: sA[k][row], pad 260
    __shared__ float4 sB[KT][16];    // W tile: sB[k][j4] covering 64 cols

    const int t    = threadIdx.x;
    const int tx   = t & 7;          // col group: cols tx*8 .. tx*8+7
    const int ty   = t >> 3;         // row group: rows ty*8 .. ty*8+7 (0..31)
    const int row0 = blockIdx.x * 256;

    unsigned long long acc[8][4];
#pragma unroll
    for (int i = 0; i < 8; i++)
#pragma unroll
        for (int p = 0; p < 4; p++) acc[i][p] = 0ull;

    const int lr = t >> 2;           // A-load: base row 0..63 (+q*64)
    const int lc = (t & 3) * 4;      // A-load: k offset 0,4,8,12

    for (int k0 = 0; k0 < K; k0 += KT) {
        // load A tile (transposed into smem)
#pragma unroll
        for (int q = 0; q < 4; q++) {
            int r = lr + q * 64;
            int g = row0 + r;
            float4 v = make_float4(0.f, 0.f, 0.f, 0.f);
            if (g < nRows)
                v = *reinterpret_cast<const float4*>(A + (size_t)g * K + k0 + lc);
            sA[lc + 0][r] = v.x;
            sA[lc + 1][r] = v.y;
            sA[lc + 2][r] = v.z;
            sA[lc + 3][r] = v.w;
        }
        // load B tile
        {
            int kk = t >> 4;         // 0..15
            int j4 = t & 15;         // 0..15
            sB[kk][j4] = *reinterpret_cast<const float4*>(W + (size_t)(k0 + kk) * 64 + j4 * 4);
        }
        __syncthreads();

#pragma unroll
        for (int kk = 0; kk < KT; kk++) {
            const float4 a0 = *reinterpret_cast<const float4*>(&sA[kk][ty * 8]);
            const float4 a1 = *reinterpret_cast<const float4*>(&sA[kk][ty * 8 + 4]);
            const ulonglong2 b0 =
                reinterpret_cast<const ulonglong2*>(&sB[kk][0])[tx * 2];
            const ulonglong2 b1 =
                reinterpret_cast<const ulonglong2*>(&sB[kk][0])[tx * 2 + 1];
            float av[8] = {a0.x, a0.y, a0.z, a0.w, a1.x, a1.y, a1.z, a1.w};
#pragma unroll
            for (int i = 0; i < 8; i++) {
                unsigned long long s = splat2(av[i]);
                acc[i][0] = fma2(s, b0.x, acc[i][0]);
                acc[i][1] = fma2(s, b0.y, acc[i][1]);
                acc[i][2] = fma2(s, b1.x, acc[i][2]);
                acc[i][3] = fma2(s, b1.y, acc[i][3]);
            }
        }
        __syncthreads();
    }

    // epilogue: + bias, optional relu, store
    float bv[8];
    {
        float4 q0 = *reinterpret_cast<const float4*>(bias + tx * 8);
        float4 q1 = *reinterpret_cast<const float4*>(bias + tx * 8 + 4);
        bv[0] = q0.x; bv[1] = q0.y; bv[2] = q0.z; bv[3] = q0.w;
        bv[4] = q1.x; bv[5] = q1.y; bv[6] = q1.z; bv[7] = q1.w;
    }
#pragma unroll
    for (int i = 0; i < 8; i++) {
        int gr = row0 + ty * 8 + i;
        if (gr < nRows) {
            float v[8];
#pragma unroll
            for (int p = 0; p < 4; p++) {
                float lo, hi;
                unpack2(acc[i][p], lo, hi);
                v[2 * p]     = lo + bv[2 * p];
                v[2 * p + 1] = hi + bv[2 * p + 1];
            }
            if (RELU) {
#pragma unroll
                for (int j = 0; j < 8; j++) v[j] = fmaxf(v[j], 0.f);
            }
            float4* o = reinterpret_cast<float4*>(out + (size_t)gr * 64 + tx * 8);
            o[0] = make_float4(v[0], v[1], v[2], v[3]);
            o[1] = make_float4(v[4], v[5], v[6], v[7]);
        }
    }
}

// ---------------------------------------------------------------------------
// Edge scatter: out[dst] += support[src] * w, 16 threads per edge (float4 each).
// support (51 MB) and out (51 MB) are both L2-resident. Vector atomics cut
// L2 atomic op count 4x vs scalar atomicAdd.
// ---------------------------------------------------------------------------
__global__ void __launch_bounds__(256)
edge_kernel(const float* __restrict__ support, const int* __restrict__ src,
            const int* __restrict__ dst, const float* __restrict__ w,
            float* __restrict__ out, int E)
{
    int g   = blockIdx.x * 256 + threadIdx.x;
    int e   = g >> 4;
    int sub = g & 15;
    if (e >= E) return;
    int   s  = src[e];
    int   d  = dst[e];
    float wt = w[e];
    float4 v = *reinterpret_cast<const float4*>(support + (size_t)s * 64 + sub * 4);
    float* o = out + (size_t)d * 64 + sub * 4;
    asm volatile("red.global.add.v4.f32 [%0], {%1, %2, %3, %4};"
                 :: "l"(o), "f"(v.x * wt), "f"(v.y * wt),
                    "f"(v.z * wt), "f"(v.w * wt)
                 : "memory");
}

// ---------------------------------------------------------------------------
__global__ void __launch_bounds__(256)
zero_kernel(float4* __restrict__ out, int n4)
{
    int i = blockIdx.x * 256 + threadIdx.x;
    if (i < n4) out[i] = make_float4(0.f, 0.f, 0.f, 0.f);
}

// warp per row: L2-normalize rows of 64 (matches jnp: row / max(||row||, 1e-12))
__global__ void __launch_bounds__(256)
normalize_kernel(float* __restrict__ out, int N)
{
    int row  = blockIdx.x * 8 + (threadIdx.x >> 5);
    int lane = threadIdx.x & 31;
    if (row >= N) return;
    float* p = out + (size_t)row * 64;
    float2 v = *reinterpret_cast<float2*>(p + lane * 2);
    float ss = v.x * v.x + v.y * v.y;
#pragma unroll
    for (int o = 16; o > 0; o >>= 1) ss += __shfl_xor_sync(0xFFFFFFFFu, ss, o);
    float inv = 1.0f / fmaxf(sqrtf(ss), 1e-12f);
    v.x *= inv;
    v.y *= inv;
    *reinterpret_cast<float2*>(p + lane * 2) = v;
}

// ---------------------------------------------------------------------------
extern "C" void kernel_launch(void* const* d_in, const int* in_sizes, int n_in,
                              void* d_out, int out_size)
{
    const float* feat_a   = (const float*)d_in[0];
    const float* W_a      = (const float*)d_in[1];
    const float* b_a      = (const float*)d_in[2];
    const float* feat_b   = (const float*)d_in[3];
    const float* W_b      = (const float*)d_in[4];
    const float* b_b      = (const float*)d_in[5];
    const float* feat_c   = (const float*)d_in[6];
    const float* W_c      = (const float*)d_in[7];
    const float* b_c      = (const float*)d_in[8];
    const float* gcn_W    = (const float*)d_in[9];
    const float* gcn_b    = (const float*)d_in[10];
    const float* edge_w   = (const float*)d_in[11];
    const int*   edge_src = (const int*)d_in[12];
    const int*   edge_dst = (const int*)d_in[13];

    const int nA = in_sizes[0] / 512;
    const int nB = in_sizes[3] / 256;
    const int nC = in_sizes[6] / 128;
    const int N  = nA + nB + nC;
    const int E  = in_sizes[11];

    float* enc = nullptr;
    float* sup = nullptr;
    cudaGetSymbolAddress((void**)&enc, g_enc);
    cudaGetSymbolAddress((void**)&sup, g_support);

    float* out = (float*)d_out;

    // zero the accumulator (d_out is poisoned)
    {
        int n4 = N * 16;
        zero_kernel<<<(n4 + 255) / 256, 256>>>((float4*)out, n4);
    }

    // per-type encoders -> g_enc (relu)
    gemm_kernel<512, true><<<(nA + 255) / 256, 256>>>(feat_a, W_a, b_a, enc, nA);
    gemm_kernel<256, true><<<(nB + 255) / 256, 256>>>(feat_b, W_b, b_b,
                                                      enc + (size_t)nA * 64, nB);
    gemm_kernel<128, true><<<(nC + 255) / 256, 256>>>(feat_c, W_c, b_c,
                                                      enc + (size_t)(nA + nB) * 64, nC);

    // GCN linear: support = enc @ gcn_W + gcn_b
    gemm_kernel<64, false><<<(N + 255) / 256, 256>>>(enc, gcn_W, gcn_b, sup, N);

    // edge gather/scale/scatter-add into out
    {
        long long tot = (long long)E * 16;
        int blocks = (int)((tot + 255) / 256);
        edge_kernel<<<blocks, 256>>>(sup, edge_src, edge_dst, edge_w, out, E);
    }

    // row-wise L2 normalize in place
    normalize_kernel<<<(N + 7) / 8, 256>>>(out, N);
}

// round 11
// speedup vs baseline: 1.3617x; 1.3617x over previous
#include <cuda_runtime.h>
#include <cstdint>
#include <cstddef>

// ---------------------------------------------------------------------------
// NSHE: 3 per-type linear encoders (+ReLU)  ->  GCN linear  ->  edge
// gather*weight scatter-add (segment_sum)   ->  row L2-normalize.
// GEMMs use tf32 tensor cores (mma.sync m16n8k8), accumulate fp32.
// Scratch lives in __device__ globals (no allocation).
// ---------------------------------------------------------------------------

#define NMAX 200000
#define D 64

__device__ float g_enc[(size_t)NMAX * D];
__device__ float g_support[(size_t)NMAX * D];

// ---- tf32 helpers ---------------------------------------------------------
__device__ __forceinline__ float tf32_rna(float x) {
    unsigned u;
    asm("cvt.rna.tf32.f32 %0, %1;" : "=r"(u) : "f"(x));
    return __uint_as_float(u);
}

__device__ __forceinline__ void mma_tf32(float* c, const unsigned* a,
                                         const unsigned* b) {
    asm volatile(
        "mma.sync.aligned.m16n8k8.row.col.f32.tf32.tf32.f32 "
        "{%0,%1,%2,%3}, {%4,%5,%6,%7}, {%8,%9}, {%0,%1,%2,%3};"
        : "+f"(c[0]), "+f"(c[1]), "+f"(c[2]), "+f"(c[3])
        : "r"(a[0]), "r"(a[1]), "r"(a[2]), "r"(a[3]), "r"(b[0]), "r"(b[1]));
}

// ---------------------------------------------------------------------------
// GEMM: out[n,64] = act(A[n,K] @ W[K,64] + bias), tf32 tensor cores.
// Block tile 256(M) x 64(N), BK=32, 256 threads = 8 warps.
// Warp tile 32(M) x 64(N) = 2 m16-subtiles x 8 n8-subtiles of m16n8k8.
// ---------------------------------------------------------------------------
template <int K, bool RELU>
__global__ void __launch_bounds__(256, 2)
gemm_tc(const float* __restrict__ A, const float* __restrict__ W,
        const float* __restrict__ bias, float* __restrict__ out, int nRows)
{
    constexpr int BM = 256;
    constexpr int BK = 32;
    __shared__ float sA[BM][BK + 4];   // pad 36: frag reads conflict-free
    __shared__ float sB[BK][64 + 8];   // pad 72: stride%32==8 -> conflict-free

    const int t    = threadIdx.x;
    const int warp = t >> 5;
    const int lane = t & 31;
    const int row0 = blockIdx.x * BM;
    const int wrow = warp * 32;

    const int g4 = lane >> 2;  // groupID       (0..7)
    const int t4 = lane & 3;   // thread-in-grp (0..3)

    float acc[2][8][4];
#pragma unroll
    for (int mt = 0; mt < 2; mt++)
#pragma unroll
        for (int nt = 0; nt < 8; nt++)
#pragma unroll
            for (int i = 0; i < 4; i++) acc[mt][nt][i] = 0.f;

    for (int k0 = 0; k0 < K; k0 += BK) {
        // ---- load A tile: 256 rows x 32 cols = 2048 float4 ----
#pragma unroll
        for (int i = 0; i < 8; i++) {
            int idx = t + i * 256;
            int r   = idx >> 3;        // 0..255
            int f   = idx & 7;         // float4 slot 0..7
            int gr  = row0 + r;
            float4 v = make_float4(0.f, 0.f, 0.f, 0.f);
            if (gr < nRows)
                v = *reinterpret_cast<const float4*>(A + (size_t)gr * K + k0 + f * 4);
            sA[r][f * 4 + 0] = tf32_rna(v.x);
            sA[r][f * 4 + 1] = tf32_rna(v.y);
            sA[r][f * 4 + 2] = tf32_rna(v.z);
            sA[r][f * 4 + 3] = tf32_rna(v.w);
        }
        // ---- load B tile: 32 x 64 = 512 float4 ----
#pragma unroll
        for (int i = 0; i < 2; i++) {
            int idx = t + i * 256;
            int kk  = idx >> 4;        // 0..31
            int f   = idx & 15;        // 0..15
            float4 v = *reinterpret_cast<const float4*>(W + (size_t)(k0 + kk) * 64 + f * 4);
            sB[kk][f * 4 + 0] = tf32_rna(v.x);
            sB[kk][f * 4 + 1] = tf32_rna(v.y);
            sB[kk][f * 4 + 2] = tf32_rna(v.z);
            sB[kk][f * 4 + 3] = tf32_rna(v.w);
        }
        __syncthreads();

#pragma unroll
        for (int k8 = 0; k8 < BK / 8; k8++) {
            unsigned bf[8][2];
#pragma unroll
            for (int nt = 0; nt < 8; nt++) {
                bf[nt][0] = __float_as_uint(sB[k8 * 8 + t4    ][nt * 8 + g4]);
                bf[nt][1] = __float_as_uint(sB[k8 * 8 + t4 + 4][nt * 8 + g4]);
            }
#pragma unroll
            for (int mt = 0; mt < 2; mt++) {
                unsigned af[4];
                int r = wrow + mt * 16 + g4;
                af[0] = __float_as_uint(sA[r    ][k8 * 8 + t4    ]);
                af[1] = __float_as_uint(sA[r + 8][k8 * 8 + t4    ]);
                af[2] = __float_as_uint(sA[r    ][k8 * 8 + t4 + 4]);
                af[3] = __float_as_uint(sA[r + 8][k8 * 8 + t4 + 4]);
#pragma unroll
                for (int nt = 0; nt < 8; nt++)
                    mma_tf32(acc[mt][nt], af, bf[nt]);
            }
        }
        __syncthreads();
    }

    // ---- epilogue: + bias, optional relu, float2 stores ----
#pragma unroll
    for (int nt = 0; nt < 8; nt++) {
        int col  = nt * 8 + 2 * t4;
        float b0 = bias[col];
        float b1 = bias[col + 1];
#pragma unroll
        for (int mt = 0; mt < 2; mt++) {
#pragma unroll
            for (int h = 0; h < 2; h++) {
                int gr = row0 + wrow + mt * 16 + g4 + h * 8;
                if (gr < nRows) {
                    float x0 = acc[mt][nt][h * 2 + 0] + b0;
                    float x1 = acc[mt][nt][h * 2 + 1] + b1;
                    if (RELU) {
                        x0 = fmaxf(x0, 0.f);
                        x1 = fmaxf(x1, 0.f);
                    }
                    *reinterpret_cast<float2*>(out + (size_t)gr * 64 + col) =
                        make_float2(x0, x1);
                }
            }
        }
    }
}

// ---------------------------------------------------------------------------
// Edge scatter: out[dst] += support[src] * w, 16 threads per edge (float4 each).
// support (51 MB) and out (51 MB) are both L2-resident. Vector atomics cut
// L2 atomic op count 4x vs scalar atomicAdd.
// ---------------------------------------------------------------------------
__global__ void __launch_bounds__(256)
edge_kernel(const float* __restrict__ support, const int* __restrict__ src,
            const int* __restrict__ dst, const float* __restrict__ w,
            float* __restrict__ out, int E)
{
    int g   = blockIdx.x * 256 + threadIdx.x;
    int e   = g >> 4;
    int sub = g & 15;
    if (e >= E) return;
    int   s  = src[e];
    int   d  = dst[e];
    float wt = w[e];
    float4 v = *reinterpret_cast<const float4*>(support + (size_t)s * 64 + sub * 4);
    float* o = out + (size_t)d * 64 + sub * 4;
    asm volatile("red.global.add.v4.f32 [%0], {%1, %2, %3, %4};"
                 :: "l"(o), "f"(v.x * wt), "f"(v.y * wt),
                    "f"(v.z * wt), "f"(v.w * wt)
                 : "memory");
}

// ---------------------------------------------------------------------------
__global__ void __launch_bounds__(256)
zero_kernel(float4* __restrict__ out, int n4)
{
    int i = blockIdx.x * 256 + threadIdx.x;
    if (i < n4) out[i] = make_float4(0.f, 0.f, 0.f, 0.f);
}

// warp per row: L2-normalize rows of 64 (matches jnp: row / max(||row||, 1e-12))
__global__ void __launch_bounds__(256)
normalize_kernel(float* __restrict__ out, int N)
{
    int row  = blockIdx.x * 8 + (threadIdx.x >> 5);
    int lane = threadIdx.x & 31;
    if (row >= N) return;
    float* p = out + (size_t)row * 64;
    float2 v = *reinterpret_cast<float2*>(p + lane * 2);
    float ss = v.x * v.x + v.y * v.y;
#pragma unroll
    for (int o = 16; o > 0; o >>= 1) ss += __shfl_xor_sync(0xFFFFFFFFu, ss, o);
    float inv = 1.0f / fmaxf(sqrtf(ss), 1e-12f);
    v.x *= inv;
    v.y *= inv;
    *reinterpret_cast<float2*>(p + lane * 2) = v;
}

// ---------------------------------------------------------------------------
extern "C" void kernel_launch(void* const* d_in, const int* in_sizes, int n_in,
                              void* d_out, int out_size)
{
    const float* feat_a   = (const float*)d_in[0];
    const float* W_a      = (const float*)d_in[1];
    const float* b_a      = (const float*)d_in[2];
    const float* feat_b   = (const float*)d_in[3];
    const float* W_b      = (const float*)d_in[4];
    const float* b_b      = (const float*)d_in[5];
    const float* feat_c   = (const float*)d_in[6];
    const float* W_c      = (const float*)d_in[7];
    const float* b_c      = (const float*)d_in[8];
    const float* gcn_W    = (const float*)d_in[9];
    const float* gcn_b    = (const float*)d_in[10];
    const float* edge_w   = (const float*)d_in[11];
    const int*   edge_src = (const int*)d_in[12];
    const int*   edge_dst = (const int*)d_in[13];

    const int nA = in_sizes[0] / 512;
    const int nB = in_sizes[3] / 256;
    const int nC = in_sizes[6] / 128;
    const int N  = nA + nB + nC;
    const int E  = in_sizes[11];

    float* enc = nullptr;
    float* sup = nullptr;
    cudaGetSymbolAddress((void**)&enc, g_enc);
    cudaGetSymbolAddress((void**)&sup, g_support);

    float* out = (float*)d_out;

    // zero the accumulator (d_out is poisoned)
    {
        int n4 = N * 16;
        zero_kernel<<<(n4 + 255) / 256, 256>>>((float4*)out, n4);
    }

    // per-type encoders -> g_enc (relu), tf32 tensor cores
    gemm_tc<512, true><<<(nA + 255) / 256, 256>>>(feat_a, W_a, b_a, enc, nA);
    gemm_tc<256, true><<<(nB + 255) / 256, 256>>>(feat_b, W_b, b_b,
                                                  enc + (size_t)nA * 64, nB);
    gemm_tc<128, true><<<(nC + 255) / 256, 256>>>(feat_c, W_c, b_c,
                                                  enc + (size_t)(nA + nB) * 64, nC);

    // GCN linear: support = enc @ gcn_W + gcn_b
    gemm_tc<64, false><<<(N + 255) / 256, 256>>>(enc, gcn_W, gcn_b, sup, N);

    // edge gather/scale/scatter-add into out
    {
        long long tot = (long long)E * 16;
        int blocks = (int)((tot + 255) / 256);
        edge_kernel<<<blocks, 256>>>(sup, edge_src, edge_dst, edge_w, out, E);
    }

    // row-wise L2 normalize in place
    normalize_kernel<<<(N + 7) / 8, 256>>>(out, N);
}

// round 12
// speedup vs baseline: 1.3834x; 1.0159x over previous
#include <cuda_runtime.h>
#include <cstdint>
#include <cstddef>

// ---------------------------------------------------------------------------
// NSHE: 3 per-type linear encoders (+ReLU)  ->  GCN linear  ->  edge
// gather*weight scatter-add (segment_sum)   ->  row L2-normalize.
// GEMMs use tf32 tensor cores (mma.sync m16n8k8), accumulate fp32.
// Scratch lives in __device__ globals (no allocation).
// ---------------------------------------------------------------------------

#define NMAX 200000
#define D 64

__device__ float g_enc[(size_t)NMAX * D];
__device__ float g_support[(size_t)NMAX * D];

// ---- tf32 helpers ---------------------------------------------------------
__device__ __forceinline__ float tf32_rna(float x) {
    unsigned u;
    asm("cvt.rna.tf32.f32 %0, %1;" : "=r"(u) : "f"(x));
    return __uint_as_float(u);
}

__device__ __forceinline__ void mma_tf32(float* c, const unsigned* a,
                                         const unsigned* b) {
    asm volatile(
        "mma.sync.aligned.m16n8k8.row.col.f32.tf32.tf32.f32 "
        "{%0,%1,%2,%3}, {%4,%5,%6,%7}, {%8,%9}, {%0,%1,%2,%3};"
        : "+f"(c[0]), "+f"(c[1]), "+f"(c[2]), "+f"(c[3])
        : "r"(a[0]), "r"(a[1]), "r"(a[2]), "r"(a[3]), "r"(b[0]), "r"(b[1]));
}

// ---------------------------------------------------------------------------
// GEMM: out[n,64] = act(A[n,K] @ W[K,64] + bias), tf32 tensor cores.
// Block tile 256(M) x 64(N), BK=32, 256 threads = 8 warps.
// Warp tile 32(M) x 64(N) = 2 m16-subtiles x 8 n8-subtiles of m16n8k8.
// ---------------------------------------------------------------------------
template <int K, bool RELU>
__global__ void __launch_bounds__(256, 2)
gemm_tc(const float* __restrict__ A, const float* __restrict__ W,
        const float* __restrict__ bias, float* __restrict__ out, int nRows)
{
    constexpr int BM = 256;
    constexpr int BK = 32;
    __shared__ float sA[BM][BK + 4];   // pad 36: frag reads conflict-free
    __shared__ float sB[BK][64 + 8];   // pad 72: stride%32==8 -> conflict-free

    const int t    = threadIdx.x;
    const int warp = t >> 5;
    const int lane = t & 31;
    const int row0 = blockIdx.x * BM;
    const int wrow = warp * 32;

    const int g4 = lane >> 2;  // groupID       (0..7)
    const int t4 = lane & 3;   // thread-in-grp (0..3)

    float acc[2][8][4];
#pragma unroll
    for (int mt = 0; mt < 2; mt++)
#pragma unroll
        for (int nt = 0; nt < 8; nt++)
#pragma unroll
            for (int i = 0; i < 4; i++) acc[mt][nt][i] = 0.f;

    for (int k0 = 0; k0 < K; k0 += BK) {
        // ---- load A tile: 256 rows x 32 cols = 2048 float4 ----
#pragma unroll
        for (int i = 0; i < 8; i++) {
            int idx = t + i * 256;
            int r   = idx >> 3;        // 0..255
            int f   = idx & 7;         // float4 slot 0..7
            int gr  = row0 + r;
            float4 v = make_float4(0.f, 0.f, 0.f, 0.f);
            if (gr < nRows)
                v = *reinterpret_cast<const float4*>(A + (size_t)gr * K + k0 + f * 4);
            sA[r][f * 4 + 0] = tf32_rna(v.x);
            sA[r][f * 4 + 1] = tf32_rna(v.y);
            sA[r][f * 4 + 2] = tf32_rna(v.z);
            sA[r][f * 4 + 3] = tf32_rna(v.w);
        }
        // ---- load B tile: 32 x 64 = 512 float4 ----
#pragma unroll
        for (int i = 0; i < 2; i++) {
            int idx = t + i * 256;
            int kk  = idx >> 4;        // 0..31
            int f   = idx & 15;        // 0..15
            float4 v = *reinterpret_cast<const float4*>(W + (size_t)(k0 + kk) * 64 + f * 4);
            sB[kk][f * 4 + 0] = tf32_rna(v.x);
            sB[kk][f * 4 + 1] = tf32_rna(v.y);
            sB[kk][f * 4 + 2] = tf32_rna(v.z);
            sB[kk][f * 4 + 3] = tf32_rna(v.w);
        }
        __syncthreads();

#pragma unroll
        for (int k8 = 0; k8 < BK / 8; k8++) {
            unsigned bf[8][2];
#pragma unroll
            for (int nt = 0; nt < 8; nt++) {
                bf[nt][0] = __float_as_uint(sB[k8 * 8 + t4    ][nt * 8 + g4]);
                bf[nt][1] = __float_as_uint(sB[k8 * 8 + t4 + 4][nt * 8 + g4]);
            }
#pragma unroll
            for (int mt = 0; mt < 2; mt++) {
                unsigned af[4];
                int r = wrow + mt * 16 + g4;
                af[0] = __float_as_uint(sA[r    ][k8 * 8 + t4    ]);
                af[1] = __float_as_uint(sA[r + 8][k8 * 8 + t4    ]);
                af[2] = __float_as_uint(sA[r    ][k8 * 8 + t4 + 4]);
                af[3] = __float_as_uint(sA[r + 8][k8 * 8 + t4 + 4]);
#pragma unroll
                for (int nt = 0; nt < 8; nt++)
                    mma_tf32(acc[mt][nt], af, bf[nt]);
            }
        }
        __syncthreads();
    }

    // ---- epilogue: + bias, optional relu, float2 stores ----
#pragma unroll
    for (int nt = 0; nt < 8; nt++) {
        int col  = nt * 8 + 2 * t4;
        float b0 = bias[col];
        float b1 = bias[col + 1];
#pragma unroll
        for (int mt = 0; mt < 2; mt++) {
#pragma unroll
            for (int h = 0; h < 2; h++) {
                int gr = row0 + wrow + mt * 16 + g4 + h * 8;
                if (gr < nRows) {
                    float x0 = acc[mt][nt][h * 2 + 0] + b0;
                    float x1 = acc[mt][nt][h * 2 + 1] + b1;
                    if (RELU) {
                        x0 = fmaxf(x0, 0.f);
                        x1 = fmaxf(x1, 0.f);
                    }
                    *reinterpret_cast<float2*>(out + (size_t)gr * 64 + col) =
                        make_float2(x0, x1);
                }
            }
        }
    }
}

// ---------------------------------------------------------------------------
// Edge scatter: out[dst] += support[src] * w, 16 threads per edge (float4 each).
// support (51 MB) and out (51 MB) are both L2-resident. Vector atomics cut
// L2 atomic op count 4x vs scalar atomicAdd.
// ---------------------------------------------------------------------------
__global__ void __launch_bounds__(256)
edge_kernel(const float* __restrict__ support, const int* __restrict__ src,
            const int* __restrict__ dst, const float* __restrict__ w,
            float* __restrict__ out, int E)
{
    int g   = blockIdx.x * 256 + threadIdx.x;
    int e   = g >> 4;
    int sub = g & 15;
    if (e >= E) return;
    int   s  = src[e];
    int   d  = dst[e];
    float wt = w[e];
    float4 v = *reinterpret_cast<const float4*>(support + (size_t)s * 64 + sub * 4);
    float* o = out + (size_t)d * 64 + sub * 4;
    asm volatile("red.global.add.v4.f32 [%0], {%1, %2, %3, %4};"
                 :: "l"(o), "f"(v.x * wt), "f"(v.y * wt),
                    "f"(v.z * wt), "f"(v.w * wt)
                 : "memory");
}

// ---------------------------------------------------------------------------
__global__ void __launch_bounds__(256)
zero_kernel(float4* __restrict__ out, int n4)
{
    int i = blockIdx.x * 256 + threadIdx.x;
    if (i < n4) out[i] = make_float4(0.f, 0.f, 0.f, 0.f);
}

// warp per row: L2-normalize rows of 64 (matches jnp: row / max(||row||, 1e-12))
__global__ void __launch_bounds__(256)
normalize_kernel(float* __restrict__ out, int N)
{
    int row  = blockIdx.x * 8 + (threadIdx.x >> 5);
    int lane = threadIdx.x & 31;
    if (row >= N) return;
    float* p = out + (size_t)row * 64;
    float2 v = *reinterpret_cast<float2*>(p + lane * 2);
    float ss = v.x * v.x + v.y * v.y;
#pragma unroll
    for (int o = 16; o > 0; o >>= 1) ss += __shfl_xor_sync(0xFFFFFFFFu, ss, o);
    float inv = 1.0f / fmaxf(sqrtf(ss), 1e-12f);
    v.x *= inv;
    v.y *= inv;
    *reinterpret_cast<float2*>(p + lane * 2) = v;
}

// ---------------------------------------------------------------------------
extern "C" void kernel_launch(void* const* d_in, const int* in_sizes, int n_in,
                              void* d_out, int out_size)
{
    const float* feat_a   = (const float*)d_in[0];
    const float* W_a      = (const float*)d_in[1];
    const float* b_a      = (const float*)d_in[2];
    const float* feat_b   = (const float*)d_in[3];
    const float* W_b      = (const float*)d_in[4];
    const float* b_b      = (const float*)d_in[5];
    const float* feat_c   = (const float*)d_in[6];
    const float* W_c      = (const float*)d_in[7];
    const float* b_c      = (const float*)d_in[8];
    const float* gcn_W    = (const float*)d_in[9];
    const float* gcn_b    = (const float*)d_in[10];
    const float* edge_w   = (const float*)d_in[11];
    const int*   edge_src = (const int*)d_in[12];
    const int*   edge_dst = (const int*)d_in[13];

    const int nA = in_sizes[0] / 512;
    const int nB = in_sizes[3] / 256;
    const int nC = in_sizes[6] / 128;
    const int N  = nA + nB + nC;
    const int E  = in_sizes[11];

    float* enc = nullptr;
    float* sup = nullptr;
    cudaGetSymbolAddress((void**)&enc, g_enc);
    cudaGetSymbolAddress((void**)&sup, g_support);

    float* out = (float*)d_out;

    // zero the accumulator (d_out is poisoned)
    {
        int n4 = N * 16;
        zero_kernel<<<(n4 + 255) / 256, 256>>>((float4*)out, n4);
    }

    // per-type encoders -> g_enc (relu), tf32 tensor cores
    gemm_tc<512, true><<<(nA + 255) / 256, 256>>>(feat_a, W_a, b_a, enc, nA);
    gemm_tc<256, true><<<(nB + 255) / 256, 256>>>(feat_b, W_b, b_b,
                                                  enc + (size_t)nA * 64, nB);
    gemm_tc<128, true><<<(nC + 255) / 256, 256>>>(feat_c, W_c, b_c,
                                                  enc + (size_t)(nA + nB) * 64, nC);

    // GCN linear: support = enc @ gcn_W + gcn_b
    gemm_tc<64, false><<<(N + 255) / 256, 256>>>(enc, gcn_W, gcn_b, sup, N);

    // edge gather/scale/scatter-add into out
    {
        long long tot = (long long)E * 16;
        int blocks = (int)((tot + 255) / 256);
        edge_kernel<<<blocks, 256>>>(sup, edge_src, edge_dst, edge_w, out, E);
    }

    // row-wise L2 normalize in place
    normalize_kernel<<<(N + 7) / 8, 256>>>(out, N);
}